// round 6
// baseline (speedup 1.0000x reference)
#include <cuda_runtime.h>
#include <cuda_bf16.h>

#define M_NODES 50000
#define DFEAT   128
#define N_EDGE  800000
#define NPW     8     // nodes per warp in fused SpMM

// scratch for support = X @ W  (25.6 MB, static device global — no allocs)
__device__ float g_support[(size_t)M_NODES * DFEAT];

// packed fp32x2 helpers (sm_100+ FFMA2 path — ptxas never auto-fuses)
#define FMA_F32X2(d, a, b, c) \
    asm("fma.rn.f32x2 %0, %1, %2, %3;" : "=l"(d) : "l"(a), "l"(b), "l"(c))
#define PACK2(d, lo, hi) \
    asm("mov.b64 %0, {%1, %2};" : "=l"(d) : "f"(lo), "f"(hi))
#define UNPACK2(lo, hi, d) \
    asm("mov.b64 {%0, %1}, %2;" : "=f"(lo), "=f"(hi) : "l"(d))

// ---------------------------------------------------------------------------
// Kernel 1: SGEMM  g_support = X @ W    (M=50000, N=K=128)
// 128x128 block tile, BK=8, 256 threads, 8x8 microtile per thread.
// Global->register prefetch double-buffering + packed f32x2 FMA (2x fp32 rate).
// ---------------------------------------------------------------------------
__global__ __launch_bounds__(256) void gemm_kernel(const float* __restrict__ A,
                                                   const float* __restrict__ B) {
    __shared__ float As[8][128];   // transposed A tile
    __shared__ float Bs[8][128];

    const int tid = threadIdx.x;
    const int block_row = blockIdx.x * 128;

    const int tx = tid & 15;        // 0..15 -> 8 cols each
    const int ty = tid >> 4;        // 0..15 -> 8 rows each

    const int a_row  = tid >> 1;          // 0..127
    const int a_col4 = (tid & 1) * 4;     // 0 or 4
    const int b_row  = tid >> 5;          // 0..7
    const int b_col4 = (tid & 31) * 4;

    int g_arow = block_row + a_row;
    if (g_arow >= M_NODES) g_arow = M_NODES - 1;   // clamp; output store is guarded
    const float* Aptr = A + (long long)g_arow * DFEAT;

    // 8x4 packed accumulators (each holds cols {2j, 2j+1})
    unsigned long long acc2[8][4];
#pragma unroll
    for (int i = 0; i < 8; i++)
#pragma unroll
        for (int j = 0; j < 4; j++) acc2[i][j] = 0ull;

    // prefetch k0 = 0 tile into registers
    float4 av = *(const float4*)(Aptr + a_col4);
    float4 bv = *(const float4*)(B + (long long)b_row * DFEAT + b_col4);

    for (int k0 = 0; k0 < DFEAT; k0 += 8) {
        As[a_col4 + 0][a_row] = av.x;
        As[a_col4 + 1][a_row] = av.y;
        As[a_col4 + 2][a_row] = av.z;
        As[a_col4 + 3][a_row] = av.w;
        *(float4*)&Bs[b_row][b_col4] = bv;
        __syncthreads();

        // prefetch NEXT tile (overlaps with FMA block below)
        int kn = k0 + 8;
        if (kn < DFEAT) {
            av = *(const float4*)(Aptr + kn + a_col4);
            bv = *(const float4*)(B + (long long)(kn + b_row) * DFEAT + b_col4);
        }

#pragma unroll
        for (int kk = 0; kk < 8; kk++) {
            float4 a0 = *(const float4*)&As[kk][ty * 8 + 0];
            float4 a1 = *(const float4*)&As[kk][ty * 8 + 4];
            float4 b0 = *(const float4*)&Bs[kk][tx * 8 + 0];
            float4 b1 = *(const float4*)&Bs[kk][tx * 8 + 4];

            unsigned long long bp[4];
            PACK2(bp[0], b0.x, b0.y);
            PACK2(bp[1], b0.z, b0.w);
            PACK2(bp[2], b1.x, b1.y);
            PACK2(bp[3], b1.z, b1.w);

            float a[8] = {a0.x, a0.y, a0.z, a0.w, a1.x, a1.y, a1.z, a1.w};
#pragma unroll
            for (int i = 0; i < 8; i++) {
                unsigned long long ap;
                PACK2(ap, a[i], a[i]);
#pragma unroll
                for (int j = 0; j < 4; j++)
                    FMA_F32X2(acc2[i][j], ap, bp[j], acc2[i][j]);
            }
        }
        __syncthreads();
    }

    // write 8x8 microtile (guard rows for the 50000 % 128 tail)
#pragma unroll
    for (int i = 0; i < 8; i++) {
        int row = block_row + ty * 8 + i;
        if (row < M_NODES) {
            float* dst = g_support + (long long)row * DFEAT + tx * 8;
            float4 v0, v1;
            UNPACK2(v0.x, v0.y, acc2[i][0]);
            UNPACK2(v0.z, v0.w, acc2[i][1]);
            UNPACK2(v1.x, v1.y, acc2[i][2]);
            UNPACK2(v1.z, v1.w, acc2[i][3]);
            *(float4*)(dst + 0) = v0;
            *(float4*)(dst + 4) = v1;
        }
    }
}

// ---------------------------------------------------------------------------
// Kernel 2: fused SpMM + bias.  adj_dst is SORTED; each warp OWNS a contiguous
// dst-node range [n0, n1), binary-searches its first edge, accumulates each
// node's messages in registers, and writes out[n] = bias + acc exactly once.
// No atomics, no separate init kernel (covers nodes with zero edges too).
// Lane l owns columns [4l, 4l+4) as a float4.
// ---------------------------------------------------------------------------
__global__ __launch_bounds__(256) void spmm_kernel(const int* __restrict__ src,
                                                   const int* __restrict__ dst,
                                                   const float* __restrict__ val,
                                                   const float* __restrict__ bias,
                                                   float* __restrict__ out) {
    const int gw   = (blockIdx.x * blockDim.x + threadIdx.x) >> 5;
    const int lane = threadIdx.x & 31;

    int n0 = gw * NPW;
    if (n0 >= M_NODES) return;
    int n1 = n0 + NPW;
    if (n1 > M_NODES) n1 = M_NODES;

    // lower_bound(dst, n0) — warp-uniform binary search on sorted dst
    int lo = 0, hi = N_EDGE;
    while (lo < hi) {
        int mid = (lo + hi) >> 1;
        if (dst[mid] < n0) lo = mid + 1; else hi = mid;
    }
    int e = lo;

    const float4* sup = (const float4*)g_support;
    const float4  bb  = ((const float4*)bias)[lane];

    // current edge's dst (one load per edge; avoids re-reading in loop test)
    int d = (e < N_EDGE) ? dst[e] : M_NODES;

    for (int n = n0; n < n1; ++n) {
        float4 acc = make_float4(0.f, 0.f, 0.f, 0.f);
        while (d == n) {
            float v = val[e];                              // warp-uniform
            int   s = src[e];                              // warp-uniform
            float4 sv = sup[(long long)s * (DFEAT / 4) + lane];  // 512B coalesced gather
            acc.x = fmaf(v, sv.x, acc.x);
            acc.y = fmaf(v, sv.y, acc.y);
            acc.z = fmaf(v, sv.z, acc.z);
            acc.w = fmaf(v, sv.w, acc.w);
            ++e;
            d = (e < N_EDGE) ? dst[e] : M_NODES;
        }
        float4 o = make_float4(bb.x + acc.x, bb.y + acc.y,
                               bb.z + acc.z, bb.w + acc.w);
        *(float4*)(out + (long long)n * DFEAT + lane * 4) = o;
    }
}

// ---------------------------------------------------------------------------
// inputs (metadata order): x[f32 50000*128], adj_src[i32 800000],
//   adj_dst[i32 800000], adj_val[f32 800000], weight[f32 128*128], bias[f32 128]
// output: f32 50000*128
// ---------------------------------------------------------------------------
extern "C" void kernel_launch(void* const* d_in, const int* in_sizes, int n_in,
                              void* d_out, int out_size) {
    const float* x       = (const float*)d_in[0];
    const int*   adj_src = (const int*)d_in[1];
    const int*   adj_dst = (const int*)d_in[2];
    const float* adj_val = (const float*)d_in[3];
    const float* weight  = (const float*)d_in[4];
    const float* bias    = (const float*)d_in[5];
    float*       out     = (float*)d_out;

    // 1) support = X @ W
    {
        int grid = (M_NODES + 127) / 128;   // 391
        gemm_kernel<<<grid, 256>>>(x, weight);
    }
    // 2) out = bias + A_sp @ support   (fused, no atomics)
    {
        int nwarps  = (M_NODES + NPW - 1) / NPW;              // 6250
        int threads = 256;
        int grid    = (nwarps * 32 + threads - 1) / threads;  // 782
        spmm_kernel<<<grid, threads>>>(adj_src, adj_dst, adj_val, bias, out);
    }
}